// round 10
// baseline (speedup 1.0000x reference)
#include <cuda_runtime.h>
#include <cstdint>

// VQExpert fused kernel, round 10.
// R9 numerics, RPW 8 -> 12 (register-file reuse between phase A and C peaks):
// weight/codebook LDS amortized over 12 rows; phase C as two half-codebook
// sweeps with da[12][4]; cn hoisted to registers; cp.async staging kept.

typedef unsigned long long ull;
#define FULLMASK 0xffffffffu

constexpr int NROW   = 500000;
constexpr int WARPS  = 12;
constexpr int RPW    = 12;
constexpr int TILE   = WARPS * RPW;              // 144
constexpr int NTILES = (NROW + TILE - 1) / TILE; // 3473

// smem layout (floats)
constexpr int O_WD2 = 0;          // 128x128: [(k>>1)*256 + j*2 + (k&1)]
constexpr int O_WP2 = 16384;      // 32x128 quad-packed: [(k>>2)*128 + c*4 + (k&3)]
constexpr int O_CB  = 20480;      // codebook quad-packed: [(d>>2)*1024 + c*4 + (d&3)]
constexpr int O_CN  = 28672;      // 256 code norms
constexpr int O_BD  = 28928;
constexpr int O_BP  = 29056;
constexpr int O_TS  = 29088;                      // 12 warps x (12 rows x 128) x/h stripes
constexpr int O_ZA  = O_TS + WARPS * RPW * 128;   // 12 warps x (12 rows x 32) z
constexpr int SMEM_FLOATS = O_ZA + WARPS * RPW * 32;  // 52128
constexpr int SMEM_BYTES  = SMEM_FLOATS * 4;          // 208,512 B

__device__ float g_T[256 * 128];   // fused codebook->output table (bias folded)

__device__ __forceinline__ ull ffma2(ull a, ull b, ull c) {
    ull d;
    asm("fma.rn.f32x2 %0, %1, %2, %3;" : "=l"(d) : "l"(a), "l"(b), "l"(c));
    return d;
}
__device__ __forceinline__ float f2sum(ull v) {
    float a, b;
    asm("mov.b64 {%0, %1}, %2;" : "=f"(a), "=f"(b) : "l"(v));
    return a + b;
}
__device__ __forceinline__ void cpa16(uint32_t daddr, const void* g) {
    asm volatile("cp.async.ca.shared.global [%0], [%1], 16;" :: "r"(daddr), "l"(g));
}
__device__ __forceinline__ void cpa_commit() {
    asm volatile("cp.async.commit_group;");
}
__device__ __forceinline__ void cpa_wait0() {
    asm volatile("cp.async.wait_group 0;");
}
// monotone order-preserving float->uint key (lower float <=> lower uint)
__device__ __forceinline__ unsigned fkey(float s) {
    unsigned u = __float_as_uint(s);
    return u ^ ((u >> 31) ? 0xFFFFFFFFu : 0x80000000u);
}

// ---------------- prologue: build T with bias folded ----------------
__global__ void __launch_bounds__(128)
vq_precompute_kernel(const float* __restrict__ cb,
                     const float* __restrict__ Wo, const float* __restrict__ bo,
                     const float* __restrict__ Wu, const float* __restrict__ bu)
{
    __shared__ float v[128];
    const int i = threadIdx.x;
    const int c = blockIdx.x;
    float s = 0.f;
    #pragma unroll 8
    for (int d = 0; d < 32; d++) s = fmaf(cb[c * 32 + d], Wo[i * 32 + d], s);
    v[i] = s;
    __syncthreads();
    float t = 0.f, Bi = bu[i];
    #pragma unroll 8
    for (int j = 0; j < 128; j++) {
        t  = fmaf(v[j],  Wu[i * 128 + j], t);
        Bi = fmaf(bo[j], Wu[i * 128 + j], Bi);
    }
    g_T[c * 128 + i] = t + Bi;
}

// ---------------- main kernel ----------------
__global__ void __launch_bounds__(384, 1)
vq_expert_kernel(const float* __restrict__ x,
                 const float* __restrict__ Wd, const float* __restrict__ bd,
                 const float* __restrict__ Wp, const float* __restrict__ bp,
                 const float* __restrict__ cb,
                 float* __restrict__ out)
{
    extern __shared__ float sm[];
    const int tid = threadIdx.x;

    for (int i = tid; i < 128 * 128; i += 384) {
        int j = i >> 7, k = i & 127;
        sm[O_WD2 + (k >> 1) * 256 + j * 2 + (k & 1)] = Wd[i];
    }
    for (int i = tid; i < 4096; i += 384) {
        int c = i >> 7, k = i & 127;
        sm[O_WP2 + (k >> 2) * 128 + c * 4 + (k & 3)] = Wp[i];
    }
    for (int i = tid; i < 256 * 32; i += 384) {
        int c = i >> 5, d = i & 31;
        sm[O_CB + (d >> 2) * 1024 + c * 4 + (d & 3)] = cb[i];
    }
    for (int c = tid; c < 256; c += 384) {
        float s = 0.f;
        #pragma unroll 8
        for (int d = 0; d < 32; d++) { float v = cb[c * 32 + d]; s = fmaf(v, v, s); }
        sm[O_CN + c] = s;
    }
    if (tid < 128) sm[O_BD + tid] = bd[tid];
    else if (tid < 160) sm[O_BP + tid - 128] = bp[tid - 128];
    if (blockIdx.x == 0 && tid == 0)
        out[(size_t)NROW * 128 + NROW] = 0.0f;    // commit_loss == 0 exactly
    __syncthreads();

    const int wid  = tid >> 5;
    const int lane = tid & 31;
    float* myts = sm + O_TS + wid * (RPW * 128);
    float* myza = sm + O_ZA + wid * (RPW * 32);

    const float2 bd0 = *(const float2*)(sm + O_BD + 2 * lane);
    const float2 bd1 = *(const float2*)(sm + O_BD + 64 + 2 * lane);
    const float  bpv = sm[O_BP + lane];
    float cnr[8];
    #pragma unroll
    for (int i = 0; i < 8; i++) cnr[i] = sm[O_CN + i * 32 + lane];

    float* outY = out;
    float* outI = out + (size_t)NROW * 128;
    const int tstride = gridDim.x;

    uint32_t sb = (uint32_t)__cvta_generic_to_shared(myts + 4 * lane);

    // prefetch tile 0
    {
        int row0 = blockIdx.x * TILE + wid * RPW;
        #pragma unroll
        for (int r = 0; r < RPW; r++)
            if (row0 + r < NROW)
                cpa16(sb + r * 512, x + (size_t)(row0 + r) * 128 + 4 * lane);
        cpa_commit();
    }

    for (int tile = blockIdx.x; tile < NTILES; tile += tstride) {
        const int row0 = tile * TILE + wid * RPW;
        cpa_wait0();
        __syncwarp();
        if (row0 >= NROW) { cpa_commit(); continue; }
        const bool full = (row0 + RPW <= NROW);

        // -------- phase A: h = x @ Wd^T (+bd) --------
        ull acc[RPW][4];
        #pragma unroll
        for (int r = 0; r < RPW; r++)
            #pragma unroll
            for (int t = 0; t < 4; t++) acc[r][t] = 0ull;

        for (int pp = 0; pp < 32; pp++) {
            const float* b0 = sm + O_WD2 + (2 * pp) * 256;
            const float* b1 = b0 + 256;
            ulonglong2 wa0 = *(const ulonglong2*)(b0 + 4 * lane);
            ulonglong2 wb0 = *(const ulonglong2*)(b0 + 128 + 4 * lane);
            ulonglong2 wa1 = *(const ulonglong2*)(b1 + 4 * lane);
            ulonglong2 wb1 = *(const ulonglong2*)(b1 + 128 + 4 * lane);
            #pragma unroll
            for (int r = 0; r < RPW; r++) {
                ulonglong2 xv = *(const ulonglong2*)(myts + r * 128 + 4 * pp);
                acc[r][0] = ffma2(xv.x, wa0.x, acc[r][0]);
                acc[r][1] = ffma2(xv.x, wa0.y, acc[r][1]);
                acc[r][2] = ffma2(xv.x, wb0.x, acc[r][2]);
                acc[r][3] = ffma2(xv.x, wb0.y, acc[r][3]);
                acc[r][0] = ffma2(xv.y, wa1.x, acc[r][0]);
                acc[r][1] = ffma2(xv.y, wa1.y, acc[r][1]);
                acc[r][2] = ffma2(xv.y, wb1.x, acc[r][2]);
                acc[r][3] = ffma2(xv.y, wb1.y, acc[r][3]);
            }
        }
        __syncwarp();
        #pragma unroll
        for (int r = 0; r < RPW; r++) {
            float2 h0, h1;
            h0.x = bd0.x + f2sum(acc[r][0]);
            h0.y = bd0.y + f2sum(acc[r][1]);
            h1.x = bd1.x + f2sum(acc[r][2]);
            h1.y = bd1.y + f2sum(acc[r][3]);
            *(float2*)(myts + r * 128 + 2 * lane) = h0;
            *(float2*)(myts + r * 128 + 64 + 2 * lane) = h1;
        }
        __syncwarp();

        // -------- phase B: z = h @ Wp^T (+bp), lane = z-column --------
        ull za[RPW];
        #pragma unroll
        for (int r = 0; r < RPW; r++) za[r] = 0ull;
        #pragma unroll 2
        for (int kq = 0; kq < 32; kq++) {
            ulonglong2 w = *(const ulonglong2*)(sm + O_WP2 + kq * 128 + 4 * lane);
            #pragma unroll
            for (int r = 0; r < RPW; r++) {
                ulonglong2 h2 = *(const ulonglong2*)(myts + r * 128 + 4 * kq);
                za[r] = ffma2(h2.x, w.x, za[r]);
                za[r] = ffma2(h2.y, w.y, za[r]);
            }
        }
        __syncwarp();        // all lanes done reading h -> stripe is dead
        #pragma unroll
        for (int r = 0; r < RPW; r++)
            myza[r * 32 + lane] = bpv + f2sum(za[r]);   // z to its own area
        __syncwarp();

        // prefetch NEXT tile's x into the (now dead) stripe; hidden by phase C
        {
            int nrow0 = (tile + tstride) * TILE + wid * RPW;
            #pragma unroll
            for (int r = 0; r < RPW; r++)
                if (nrow0 + r < NROW)
                    cpa16(sb + r * 512, x + (size_t)(nrow0 + r) * 128 + 4 * lane);
            cpa_commit();
        }

        // -------- phase C: argmin_c ||c||^2 - 2 z.c, two half-codebook sweeps --------
        unsigned bkey[RPW], bidx[RPW];
        #pragma unroll
        for (int r = 0; r < RPW; r++) { bkey[r] = 0xFFFFFFFFu; bidx[r] = 0u; }

        #pragma unroll
        for (int half = 0; half < 2; half++) {
            ull da[RPW][4];
            #pragma unroll
            for (int r = 0; r < RPW; r++)
                #pragma unroll
                for (int i = 0; i < 4; i++) da[r][i] = 0ull;

            for (int dq = 0; dq < 8; dq++) {
                ulonglong2 c2[4];
                #pragma unroll
                for (int i = 0; i < 4; i++)
                    c2[i] = *(const ulonglong2*)(sm + O_CB + dq * 1024
                                + ((half * 4 + i) * 32 + lane) * 4);
                #pragma unroll
                for (int r = 0; r < RPW; r++) {
                    ulonglong2 zq = *(const ulonglong2*)(myza + r * 32 + 4 * dq);
                    #pragma unroll
                    for (int i = 0; i < 4; i++) {
                        da[r][i] = ffma2(zq.x, c2[i].x, da[r][i]);
                        da[r][i] = ffma2(zq.y, c2[i].y, da[r][i]);
                    }
                }
            }
            #pragma unroll
            for (int r = 0; r < RPW; r++) {
                #pragma unroll
                for (int i = 0; i < 4; i++) {
                    int g = half * 4 + i;
                    float s = cnr[g] - 2.0f * f2sum(da[r][i]);
                    unsigned key = fkey(s);
                    if (key < bkey[r]) { bkey[r] = key; bidx[r] = (unsigned)((g << 5) | lane); }
                }
            }
        }
        int bc[RPW];
        #pragma unroll
        for (int r = 0; r < RPW; r++) {
            unsigned m = __reduce_min_sync(FULLMASK, bkey[r]);
            unsigned cand = (bkey[r] == m) ? bidx[r] : 0xFFFFFFFFu;
            bc[r] = (int)__reduce_min_sync(FULLMASK, cand);   // warp-uniform, lowest idx
        }

        // -------- epilogue: y = clamp(T[bc], -1, 1) --------
        #pragma unroll
        for (int r = 0; r < RPW; r++) {
            if (full || row0 + r < NROW) {
                float4 t = ((const float4*)(g_T + bc[r] * 128))[lane];
                float4 y;
                y.x = fminf(fmaxf(t.x, -1.0f), 1.0f);
                y.y = fminf(fmaxf(t.y, -1.0f), 1.0f);
                y.z = fminf(fmaxf(t.z, -1.0f), 1.0f);
                y.w = fminf(fmaxf(t.w, -1.0f), 1.0f);
                ((float4*)(outY + (size_t)(row0 + r) * 128))[lane] = y;
            }
        }
        if (lane == 0) {
            #pragma unroll
            for (int r = 0; r < RPW; r++)
                if (row0 + r < NROW) outI[row0 + r] = (float)bc[r];
        }
        __syncwarp();
    }
}

extern "C" void kernel_launch(void* const* d_in, const int* in_sizes, int n_in,
                              void* d_out, int out_size)
{
    const float* x  = (const float*)d_in[0];
    const float* Wd = (const float*)d_in[1];
    const float* bd = (const float*)d_in[2];
    const float* Wp = (const float*)d_in[3];
    const float* bp = (const float*)d_in[4];
    const float* cb = (const float*)d_in[5];
    const float* Wo = (const float*)d_in[6];
    const float* bo = (const float*)d_in[7];
    const float* Wu = (const float*)d_in[8];
    const float* bu = (const float*)d_in[9];
    float* out = (float*)d_out;

    cudaFuncSetAttribute(vq_expert_kernel,
                         cudaFuncAttributeMaxDynamicSharedMemorySize, SMEM_BYTES);

    vq_precompute_kernel<<<256, 128>>>(cb, Wo, bo, Wu, bu);
    vq_expert_kernel<<<148, 384, SMEM_BYTES>>>(x, Wd, bd, Wp, bp, cb, out);
}

// round 11
// speedup vs baseline: 1.7296x; 1.7296x over previous
#include <cuda_runtime.h>
#include <cstdint>

// VQExpert fused kernel, round 11.
// Folded fast path with margin-guarded exact fallback:
//   z_f = x @ M^T + bz   (M = Wp@Wd, double-precision prologue)      64 instr/row
//   scores_f = ||c||^2 - 2 z_f.c, track best + second-best
//   if (second - best) < TH: recompute row via exact two-step (R4 path, bit-
//   identical order) and take its argmin.  TH = 4e-3 >> folded perturbation.
//   y = clamp(T[idx]) with T = (cb@Wo^T)@Wu^T + bias  [prologue]

typedef unsigned long long ull;
#define FULLMASK 0xffffffffu

constexpr int NROW   = 500000;
constexpr int WARPS  = 16;
constexpr int RPW    = 8;
constexpr int TILE   = WARPS * RPW;              // 128
constexpr int NTILES = (NROW + TILE - 1) / TILE; // 3907
constexpr float TH   = 4e-3f;

// smem layout (floats)
constexpr int O_WD2 = 0;          // 128x128 k-pair: [(k>>1)*256 + j*2 + (k&1)]  (exact path)
constexpr int O_M2  = 16384;      // 32x128 quad: [(k>>2)*128 + c*4 + (k&3)]
constexpr int O_WP2 = 20480;      // 32x128 quad
constexpr int O_CB  = 24576;      // codebook quad: [(d>>2)*1024 + c*4 + (d&3)]
constexpr int O_CN  = 32768;      // 256 code norms
constexpr int O_BD  = 33024;
constexpr int O_BP  = 33152;
constexpr int O_BZ  = 33184;
constexpr int O_TS  = 33216;                      // 16 warps x (8 rows x 128) x stays live
constexpr int O_ZA  = O_TS + WARPS * RPW * 128;   // 16 warps x (8 rows x 32) z
constexpr int O_HS  = O_ZA + WARPS * RPW * 32;    // 16 warps x 128 scratch h
constexpr int SMEM_FLOATS = O_HS + WARPS * 128;   // 55744
constexpr int SMEM_BYTES  = SMEM_FLOATS * 4;      // 222,976 B

__device__ float g_T[256 * 128];   // fused codebook->output table (bias folded)
__device__ float g_M[32 * 128];    // fused x->z projection (double-accumulated)
__device__ float g_bz[32];

__device__ __forceinline__ ull ffma2(ull a, ull b, ull c) {
    ull d;
    asm("fma.rn.f32x2 %0, %1, %2, %3;" : "=l"(d) : "l"(a), "l"(b), "l"(c));
    return d;
}
__device__ __forceinline__ float f2sum(ull v) {
    float a, b;
    asm("mov.b64 {%0, %1}, %2;" : "=f"(a), "=f"(b) : "l"(v));
    return a + b;
}
__device__ __forceinline__ void cpa16(uint32_t daddr, const void* g) {
    asm volatile("cp.async.ca.shared.global [%0], [%1], 16;" :: "r"(daddr), "l"(g));
}
__device__ __forceinline__ void cpa_commit() { asm volatile("cp.async.commit_group;"); }
__device__ __forceinline__ void cpa_wait0()  { asm volatile("cp.async.wait_group 0;"); }
// monotone float->uint key (lower float <=> lower uint) and inverse
__device__ __forceinline__ unsigned fkey(float s) {
    unsigned u = __float_as_uint(s);
    return u ^ ((u >> 31) ? 0xFFFFFFFFu : 0x80000000u);
}
__device__ __forceinline__ float kinv(unsigned k) {
    unsigned u = (k & 0x80000000u) ? (k ^ 0x80000000u) : ~k;
    return __uint_as_float(u);
}

// ---------------- prologue ----------------
__global__ void __launch_bounds__(128)
vq_precompute_kernel(const float* __restrict__ cb,
                     const float* __restrict__ Wd, const float* __restrict__ bd,
                     const float* __restrict__ Wp, const float* __restrict__ bp,
                     const float* __restrict__ Wo, const float* __restrict__ bo,
                     const float* __restrict__ Wu, const float* __restrict__ bu)
{
    __shared__ float v[128];
    const int i = threadIdx.x;
    const int c = blockIdx.x;
    if (c < 256) {
        float s = 0.f;
        #pragma unroll 8
        for (int d = 0; d < 32; d++) s = fmaf(cb[c * 32 + d], Wo[i * 32 + d], s);
        v[i] = s;
        __syncthreads();
        float t = 0.f, Bi = bu[i];
        #pragma unroll 8
        for (int j = 0; j < 128; j++) {
            t  = fmaf(v[j],  Wu[i * 128 + j], t);
            Bi = fmaf(bo[j], Wu[i * 128 + j], Bi);
        }
        g_T[c * 128 + i] = t + Bi;
    } else if (c < 288) {
        int zc = c - 256;              // M[zc][i] in double for tight folded error
        double s = 0.0;
        for (int h = 0; h < 128; h++)
            s += (double)Wp[zc * 128 + h] * (double)Wd[h * 128 + i];
        g_M[zc * 128 + i] = (float)s;
    } else if (i < 32) {
        double s = (double)bp[i];
        for (int h = 0; h < 128; h++) s += (double)Wp[i * 128 + h] * (double)bd[h];
        g_bz[i] = (float)s;
    }
}

// exact two-step recompute for one row (bit-identical order to the R4 path).
__device__ __noinline__ int exact_row(const float* sm, const float* xrow,
                                      float* hs, float* zrow, int lane,
                                      float2 bd0, float2 bd1, float bpv)
{
    ull a0 = 0, a1 = 0, a2 = 0, a3 = 0;
    for (int pp = 0; pp < 32; pp++) {
        const float* b0 = sm + O_WD2 + (2 * pp) * 256;
        const float* b1 = b0 + 256;
        ulonglong2 wa0 = *(const ulonglong2*)(b0 + 4 * lane);
        ulonglong2 wb0 = *(const ulonglong2*)(b0 + 128 + 4 * lane);
        ulonglong2 wa1 = *(const ulonglong2*)(b1 + 4 * lane);
        ulonglong2 wb1 = *(const ulonglong2*)(b1 + 128 + 4 * lane);
        ulonglong2 xv  = *(const ulonglong2*)(xrow + 4 * pp);
        a0 = ffma2(xv.x, wa0.x, a0); a1 = ffma2(xv.x, wa0.y, a1);
        a2 = ffma2(xv.x, wb0.x, a2); a3 = ffma2(xv.x, wb0.y, a3);
        a0 = ffma2(xv.y, wa1.x, a0); a1 = ffma2(xv.y, wa1.y, a1);
        a2 = ffma2(xv.y, wb1.x, a2); a3 = ffma2(xv.y, wb1.y, a3);
    }
    __syncwarp();
    hs[2 * lane]        = bd0.x + f2sum(a0);
    hs[2 * lane + 1]    = bd0.y + f2sum(a1);
    hs[64 + 2 * lane]   = bd1.x + f2sum(a2);
    hs[64 + 2 * lane + 1] = bd1.y + f2sum(a3);
    __syncwarp();
    ull zacc = 0;
    for (int kq = 0; kq < 32; kq++) {
        ulonglong2 w  = *(const ulonglong2*)(sm + O_WP2 + kq * 128 + 4 * lane);
        ulonglong2 h2 = *(const ulonglong2*)(hs + 4 * kq);
        zacc = ffma2(h2.x, w.x, zacc);
        zacc = ffma2(h2.y, w.y, zacc);
    }
    __syncwarp();
    zrow[lane] = bpv + f2sum(zacc);
    __syncwarp();
    ull dd[8];
    #pragma unroll
    for (int g = 0; g < 8; g++) dd[g] = 0ull;
    for (int dq = 0; dq < 8; dq++) {
        ulonglong2 zq = *(const ulonglong2*)(zrow + 4 * dq);
        #pragma unroll
        for (int g = 0; g < 8; g++) {
            ulonglong2 c2 = *(const ulonglong2*)(sm + O_CB + dq * 1024 + (g * 32 + lane) * 4);
            dd[g] = ffma2(zq.x, c2.x, dd[g]);
            dd[g] = ffma2(zq.y, c2.y, dd[g]);
        }
    }
    unsigned bk = 0xFFFFFFFFu, bi = 0;
    #pragma unroll
    for (int g = 0; g < 8; g++) {
        float s = sm[O_CN + g * 32 + lane] - 2.0f * f2sum(dd[g]);
        unsigned k = fkey(s);
        if (k < bk) { bk = k; bi = (unsigned)((g << 5) | lane); }
    }
    unsigned m = __reduce_min_sync(FULLMASK, bk);
    unsigned cand = (bk == m) ? bi : 0xFFFFFFFFu;
    return (int)__reduce_min_sync(FULLMASK, cand);
}

// ---------------- main kernel ----------------
__global__ void __launch_bounds__(512, 1)
vq_expert_kernel(const float* __restrict__ x,
                 const float* __restrict__ Wd, const float* __restrict__ bd,
                 const float* __restrict__ Wp, const float* __restrict__ bp,
                 const float* __restrict__ cb,
                 float* __restrict__ out)
{
    extern __shared__ float sm[];
    const int tid = threadIdx.x;

    for (int i = tid; i < 128 * 128; i += 512) {
        int j = i >> 7, k = i & 127;
        sm[O_WD2 + (k >> 1) * 256 + j * 2 + (k & 1)] = Wd[i];
    }
    for (int i = tid; i < 4096; i += 512) {
        int c = i >> 7, k = i & 127;
        sm[O_M2  + (k >> 2) * 128 + c * 4 + (k & 3)] = g_M[i];
        sm[O_WP2 + (k >> 2) * 128 + c * 4 + (k & 3)] = Wp[i];
    }
    for (int i = tid; i < 256 * 32; i += 512) {
        int c = i >> 5, d = i & 31;
        sm[O_CB + (d >> 2) * 1024 + c * 4 + (d & 3)] = cb[i];
    }
    for (int c = tid; c < 256; c += 512) {
        float s = 0.f;
        #pragma unroll 8
        for (int d = 0; d < 32; d++) { float v = cb[c * 32 + d]; s = fmaf(v, v, s); }
        sm[O_CN + c] = s;
    }
    if (tid < 128) sm[O_BD + tid] = bd[tid];
    else if (tid < 160) sm[O_BP + tid - 128] = bp[tid - 128];
    else if (tid < 192) sm[O_BZ + tid - 160] = g_bz[tid - 160];
    if (blockIdx.x == 0 && tid == 0)
        out[(size_t)NROW * 128 + NROW] = 0.0f;    // commit_loss == 0 exactly
    __syncthreads();

    const int wid  = tid >> 5;
    const int lane = tid & 31;
    float* myts = sm + O_TS + wid * (RPW * 128);
    float* myza = sm + O_ZA + wid * (RPW * 32);
    float* myhs = sm + O_HS + wid * 128;

    const float2 bd0 = *(const float2*)(sm + O_BD + 2 * lane);
    const float2 bd1 = *(const float2*)(sm + O_BD + 64 + 2 * lane);
    const float  bpv = sm[O_BP + lane];
    const float  bzv = sm[O_BZ + lane];

    float* outY = out;
    float* outI = out + (size_t)NROW * 128;

    uint32_t sb = (uint32_t)__cvta_generic_to_shared(myts + 4 * lane);

    for (int tile = blockIdx.x; tile < NTILES; tile += gridDim.x) {
        const int row0 = tile * TILE + wid * RPW;
        if (row0 >= NROW) continue;
        const bool full = (row0 + RPW <= NROW);

        // stage x (stays live through the whole tile for the exact fallback)
        #pragma unroll
        for (int r = 0; r < RPW; r++)
            if (full || row0 + r < NROW)
                cpa16(sb + r * 512, x + (size_t)(row0 + r) * 128 + 4 * lane);
        cpa_commit();
        cpa_wait0();
        __syncwarp();

        // -------- folded z: z_f = x @ M^T + bz, lane = z-column --------
        ull za[RPW];
        #pragma unroll
        for (int r = 0; r < RPW; r++) za[r] = 0ull;
        #pragma unroll 4
        for (int kq = 0; kq < 32; kq++) {
            ulonglong2 w = *(const ulonglong2*)(sm + O_M2 + kq * 128 + 4 * lane);
            #pragma unroll
            for (int r = 0; r < RPW; r++) {
                ulonglong2 xk = *(const ulonglong2*)(myts + r * 128 + 4 * kq);
                za[r] = ffma2(xk.x, w.x, za[r]);
                za[r] = ffma2(xk.y, w.y, za[r]);
            }
        }
        __syncwarp();
        #pragma unroll
        for (int r = 0; r < RPW; r++)
            myza[r * 32 + lane] = bzv + f2sum(za[r]);
        __syncwarp();

        // -------- folded argmin with best + second-best tracking --------
        unsigned bkey[RPW], skey[RPW], bidx[RPW];
        #pragma unroll
        for (int r = 0; r < RPW; r++) { bkey[r] = 0xFFFFFFFFu; skey[r] = 0xFFFFFFFFu; bidx[r] = 0u; }

        #pragma unroll
        for (int half = 0; half < 2; half++) {
            ull da[RPW][4];
            #pragma unroll
            for (int r = 0; r < RPW; r++)
                #pragma unroll
                for (int i = 0; i < 4; i++) da[r][i] = 0ull;

            #pragma unroll 2
            for (int dq = 0; dq < 8; dq++) {
                ulonglong2 c2[4];
                #pragma unroll
                for (int i = 0; i < 4; i++)
                    c2[i] = *(const ulonglong2*)(sm + O_CB + dq * 1024
                                + ((half * 4 + i) * 32 + lane) * 4);
                #pragma unroll
                for (int r = 0; r < RPW; r++) {
                    ulonglong2 zq = *(const ulonglong2*)(myza + r * 32 + 4 * dq);
                    #pragma unroll
                    for (int i = 0; i < 4; i++) {
                        da[r][i] = ffma2(zq.x, c2[i].x, da[r][i]);
                        da[r][i] = ffma2(zq.y, c2[i].y, da[r][i]);
                    }
                }
            }
            #pragma unroll
            for (int r = 0; r < RPW; r++) {
                #pragma unroll
                for (int i = 0; i < 4; i++) {
                    int g = half * 4 + i;
                    float s = sm[O_CN + g * 32 + lane] - 2.0f * f2sum(da[r][i]);
                    unsigned key = fkey(s);
                    if (key < bkey[r]) {
                        skey[r] = bkey[r]; bkey[r] = key;
                        bidx[r] = (unsigned)((g << 5) | lane);
                    } else if (key < skey[r]) skey[r] = key;
                }
            }
        }

        int bc[RPW];
        #pragma unroll
        for (int r = 0; r < RPW; r++) {
            unsigned m1 = __reduce_min_sync(FULLMASK, bkey[r]);
            unsigned c2k = (bkey[r] == m1) ? skey[r] : bkey[r];
            unsigned m2 = __reduce_min_sync(FULLMASK, c2k);
            unsigned idc = (bkey[r] == m1) ? bidx[r] : 0xFFFFFFFFu;
            int idx = (int)__reduce_min_sync(FULLMASK, idc);
            float s1 = kinv(m1), s2 = kinv(m2);
            if (s2 - s1 < TH && (full || row0 + r < NROW)) {
                // boundary row: exact two-step recompute (R4-validated path)
                idx = exact_row(sm, myts + r * 128, myhs, myza + r * 32,
                                lane, bd0, bd1, bpv);
            }
            bc[r] = idx;
        }

        // -------- epilogue: y = clamp(T[bc], -1, 1) --------
        #pragma unroll
        for (int r = 0; r < RPW; r++) {
            if (full || row0 + r < NROW) {
                float4 t = ((const float4*)(g_T + bc[r] * 128))[lane];
                float4 y;
                y.x = fminf(fmaxf(t.x, -1.0f), 1.0f);
                y.y = fminf(fmaxf(t.y, -1.0f), 1.0f);
                y.z = fminf(fmaxf(t.z, -1.0f), 1.0f);
                y.w = fminf(fmaxf(t.w, -1.0f), 1.0f);
                ((float4*)(outY + (size_t)(row0 + r) * 128))[lane] = y;
            }
        }
        if (lane == 0) {
            #pragma unroll
            for (int r = 0; r < RPW; r++)
                if (row0 + r < NROW) outI[row0 + r] = (float)bc[r];
        }
        __syncwarp();
    }
}

extern "C" void kernel_launch(void* const* d_in, const int* in_sizes, int n_in,
                              void* d_out, int out_size)
{
    const float* x  = (const float*)d_in[0];
    const float* Wd = (const float*)d_in[1];
    const float* bd = (const float*)d_in[2];
    const float* Wp = (const float*)d_in[3];
    const float* bp = (const float*)d_in[4];
    const float* cb = (const float*)d_in[5];
    const float* Wo = (const float*)d_in[6];
    const float* bo = (const float*)d_in[7];
    const float* Wu = (const float*)d_in[8];
    const float* bu = (const float*)d_in[9];
    float* out = (float*)d_out;

    cudaFuncSetAttribute(vq_expert_kernel,
                         cudaFuncAttributeMaxDynamicSharedMemorySize, SMEM_BYTES);

    vq_precompute_kernel<<<289, 128>>>(cb, Wd, bd, Wp, bp, Wo, bo, Wu, bu);
    vq_expert_kernel<<<148, 512, SMEM_BYTES>>>(x, Wd, bd, Wp, bp, cb, out);
}